// round 9
// baseline (speedup 1.0000x reference)
#include <cuda_runtime.h>
#include <cstdint>
#include <cstddef>

#define B_SZ 1024
#define DSAE 8192
#define KDIM 16384
#define KTOP 64

typedef unsigned long long ull;
typedef unsigned int uint32;

// ---------------- static scratch (no allocations allowed) ----------------
__device__ float g_pre[(size_t)B_SZ * DSAE];   // 32 MB encoder output
__device__ int   g_idx[B_SZ * KTOP];
__device__ float g_val[B_SZ * KTOP];
__device__ float g_part[B_SZ];

// ---------------- packed fp32 helpers (sm_100+) ----------------
__device__ __forceinline__ ull dup2(float a) {
    ull r; asm("mov.b64 %0,{%1,%1};" : "=l"(r) : "f"(a)); return r;
}
__device__ __forceinline__ void fma2(ull& d, ull a, ull b) {
    asm("fma.rn.f32x2 %0,%1,%2,%0;" : "+l"(d) : "l"(a), "l"(b));
}
__device__ __forceinline__ void add2(ull& d, ull a) {
    asm("add.rn.f32x2 %0,%0,%1;" : "+l"(d) : "l"(a));
}
__device__ __forceinline__ void unpk(ull v, float& lo, float& hi) {
    asm("mov.b64 {%0,%1},%2;" : "=f"(lo), "=f"(hi) : "l"(v));
}

// =====================================================================
// Kernel 1: encoder GEMM  g_pre[1024][8192] = X[1024][16384]*W[16384][8192] + b
// 128x128 tile, BK=16, 256 threads, 8x8/thread via f32x2, double-buffered,
// chunked accumulation (per-tile partial -> master) for fp32 accuracy.
// =====================================================================
__global__ void __launch_bounds__(256, 1)
enc_gemm(const float* __restrict__ X, const float* __restrict__ W,
         const float* __restrict__ bias)
{
    __shared__ __align__(16) float As[2][16][132];
    __shared__ __align__(16) float Bs[2][16][132];

    const int tid = threadIdx.x;
    const int bn = blockIdx.x;   // 0..63 (N)
    const int bm = blockIdx.y;   // 0..7  (M)
    const int tx = tid & 15;     // n-dir
    const int ty = tid >> 4;     // m-dir

    const float* Ag = X + (size_t)bm * 128 * KDIM;
    const float* Bg = W + bn * 128;

    const int ar = tid >> 2;           // 0..63
    const int ak = (tid & 3) << 2;     // 0,4,8,12
    const int bk = tid >> 5;           // 0..7
    const int bc = (tid & 31) << 2;    // 0..124

    ull mast[8][4];
#pragma unroll
    for (int i = 0; i < 8; i++)
#pragma unroll
        for (int j = 0; j < 4; j++) mast[i][j] = 0ull;

    // preload tile 0 into buffer 0
    float4 a0 = *(const float4*)(Ag + (size_t)ar * KDIM + ak);
    float4 a1 = *(const float4*)(Ag + (size_t)(ar + 64) * KDIM + ak);
    float4 b0 = *(const float4*)(Bg + (size_t)bk * DSAE + bc);
    float4 b1 = *(const float4*)(Bg + (size_t)(bk + 8) * DSAE + bc);
    As[0][ak + 0][ar] = a0.x; As[0][ak + 1][ar] = a0.y;
    As[0][ak + 2][ar] = a0.z; As[0][ak + 3][ar] = a0.w;
    As[0][ak + 0][ar + 64] = a1.x; As[0][ak + 1][ar + 64] = a1.y;
    As[0][ak + 2][ar + 64] = a1.z; As[0][ak + 3][ar + 64] = a1.w;
    *(float4*)&Bs[0][bk][bc]     = b0;
    *(float4*)&Bs[0][bk + 8][bc] = b1;
    __syncthreads();

    const int NT = KDIM / 16;   // 1024
    for (int kt = 0; kt < NT; kt++) {
        const int buf = kt & 1;
        if (kt < NT - 1) {
            const float* Ak = Ag + (size_t)(kt + 1) * 16;
            a0 = *(const float4*)(Ak + (size_t)ar * KDIM + ak);
            a1 = *(const float4*)(Ak + (size_t)(ar + 64) * KDIM + ak);
            const float* Bk = Bg + (size_t)(kt + 1) * 16 * DSAE;
            b0 = *(const float4*)(Bk + (size_t)bk * DSAE + bc);
            b1 = *(const float4*)(Bk + (size_t)(bk + 8) * DSAE + bc);
        }
        ull acc[8][4];
#pragma unroll
        for (int i = 0; i < 8; i++)
#pragma unroll
            for (int j = 0; j < 4; j++) acc[i][j] = 0ull;

#pragma unroll
        for (int k = 0; k < 16; k++) {
            float4 av0 = *(const float4*)&As[buf][k][ty * 8];
            float4 av1 = *(const float4*)&As[buf][k][ty * 8 + 4];
            ulonglong2 bb0 = *(const ulonglong2*)&Bs[buf][k][tx * 8];
            ulonglong2 bb1 = *(const ulonglong2*)&Bs[buf][k][tx * 8 + 4];
            float am[8] = {av0.x, av0.y, av0.z, av0.w, av1.x, av1.y, av1.z, av1.w};
#pragma unroll
            for (int i = 0; i < 8; i++) {
                ull ad = dup2(am[i]);
                fma2(acc[i][0], ad, bb0.x);
                fma2(acc[i][1], ad, bb0.y);
                fma2(acc[i][2], ad, bb1.x);
                fma2(acc[i][3], ad, bb1.y);
            }
        }
#pragma unroll
        for (int i = 0; i < 8; i++) {
            add2(mast[i][0], acc[i][0]); add2(mast[i][1], acc[i][1]);
            add2(mast[i][2], acc[i][2]); add2(mast[i][3], acc[i][3]);
        }

        if (kt < NT - 1) {
            const int nb = buf ^ 1;
            As[nb][ak + 0][ar] = a0.x; As[nb][ak + 1][ar] = a0.y;
            As[nb][ak + 2][ar] = a0.z; As[nb][ak + 3][ar] = a0.w;
            As[nb][ak + 0][ar + 64] = a1.x; As[nb][ak + 1][ar + 64] = a1.y;
            As[nb][ak + 2][ar + 64] = a1.z; As[nb][ak + 3][ar + 64] = a1.w;
            *(float4*)&Bs[nb][bk][bc]     = b0;
            *(float4*)&Bs[nb][bk + 8][bc] = b1;
            __syncthreads();
        }
    }

    // epilogue: add bias, write g_pre (g_pre is 16B-aligned -> float4 OK)
    const int gcol = bn * 128 + tx * 8;
    float4 be0 = *(const float4*)&bias[gcol];
    float4 be1 = *(const float4*)&bias[gcol + 4];
    float* C = g_pre + (size_t)(bm * 128 + ty * 8) * DSAE + gcol;
#pragma unroll
    for (int i = 0; i < 8; i++) {
        float4 r0, r1;
        unpk(mast[i][0], r0.x, r0.y); unpk(mast[i][1], r0.z, r0.w);
        unpk(mast[i][2], r1.x, r1.y); unpk(mast[i][3], r1.z, r1.w);
        r0.x += be0.x; r0.y += be0.y; r0.z += be0.z; r0.w += be0.w;
        r1.x += be1.x; r1.y += be1.y; r1.z += be1.z; r1.w += be1.w;
        *(float4*)(C + (size_t)i * DSAE)     = r0;
        *(float4*)(C + (size_t)i * DSAE + 4) = r1;
    }
}

// =====================================================================
// Kernel 2: exact top-64 per row via 4-level radix select on monotone keys.
// Ties broken by lowest index (matches jax.lax.top_k). Also zeros + scatters z.
// NOTE: z_out is only 4-byte aligned (offset by scalar loss) -> scalar stores.
// =====================================================================
__global__ void __launch_bounds__(256)
topk_kernel(float* __restrict__ z_out)
{
    __shared__ uint32 keys[8192];
    __shared__ uint32 hist[256];
    __shared__ uint32 tieb[256];
    __shared__ uint32 wpref[256];
    __shared__ int   s_selidx[KTOP];
    __shared__ float s_selval[KTOP];
    __shared__ uint32 s_pref, s_mask;
    __shared__ int s_kneed, s_cnt;

    const int b = blockIdx.x;
    const int tid = threadIdx.x;
    const float* pre = g_pre + (size_t)b * DSAE;
    float* zr = z_out + (size_t)b * DSAE;

    // monotone key transform + zero z row (scalar, coalesced)
    for (int i = tid; i < 8192; i += 256) {
        uint32 u = __float_as_uint(pre[i]);
        keys[i] = (u & 0x80000000u) ? ~u : (u | 0x80000000u);
        zr[i] = 0.f;
    }
    if (tid == 0) { s_pref = 0u; s_mask = 0u; s_kneed = KTOP; s_cnt = 0; }
    __syncthreads();

    for (int lvl = 0; lvl < 4; lvl++) {
        const int shift = 24 - lvl * 8;
        hist[tid] = 0u;
        __syncthreads();
        const uint32 msk = s_mask, prf = s_pref;
        for (int i = tid; i < 8192; i += 256) {
            uint32 k = keys[i];
            if ((k & msk) == prf) atomicAdd(&hist[(k >> shift) & 255u], 1u);
        }
        __syncthreads();
        if (tid == 0) {
            int need = s_kneed, cum = 0, d = 255;
            for (; d >= 0; d--) {
                int c = (int)hist[d];
                if (cum + c >= need) { s_kneed = need - cum; break; }
                cum += c;
            }
            s_pref = prf | ((uint32)d << shift);
            s_mask = msk | (0xFFu << shift);
        }
        __syncthreads();
    }

    const uint32 Kthr = s_pref;
    const int kneed = s_kneed;
    const int cgt = KTOP - kneed;   // count of strictly-greater elements
    tieb[tid] = 0u;
    __syncthreads();

    for (int i = tid; i < 8192; i += 256) {
        uint32 k = keys[i];
        if (k > Kthr) {
            int p = atomicAdd(&s_cnt, 1);
            uint32 ub = (k & 0x80000000u) ? (k ^ 0x80000000u) : ~k;
            s_selidx[p] = i;
            s_selval[p] = fmaxf(__uint_as_float(ub), 0.f);
        } else if (k == Kthr) {
            atomicOr(&tieb[i >> 5], 1u << (i & 31));
        }
    }
    __syncthreads();
    if (tid == 0) {
        uint32 run = 0;
        for (int w = 0; w < 256; w++) { wpref[w] = run; run += __popc(tieb[w]); }
    }
    __syncthreads();
    for (int i = tid; i < 8192; i += 256) {
        uint32 k = keys[i];
        if (k == Kthr) {
            int w = i >> 5;
            int rank = (int)wpref[w] + __popc(tieb[w] & ((1u << (i & 31)) - 1u));
            if (rank < kneed) {
                uint32 ub = (k & 0x80000000u) ? (k ^ 0x80000000u) : ~k;
                s_selidx[cgt + rank] = i;
                s_selval[cgt + rank] = fmaxf(__uint_as_float(ub), 0.f);
            }
        }
    }
    __syncthreads();
    if (tid < KTOP) {
        int   fi = s_selidx[tid];
        float fv = s_selval[tid];
        g_idx[b * KTOP + tid] = fi;
        g_val[b * KTOP + tid] = fv;
        zr[fi] = fv;
    }
}

// =====================================================================
// Kernel 3: sparse multi-scale decode + loss partials + last_xhat.
// One CTA per batch. 63 accumulator rows (sum of scales) x 512 cols.
// DRAM-bound gather of W_dec rows. xhat_out is 4B-aligned -> scalar stores.
// =====================================================================
__constant__ int   c_prefix[6] = {1366, 2732, 4097, 5462, 6827, 8192};
__constant__ int   c_stride[6] = {512, 1024, 2048, 4096, 8192, 16384};
__constant__ int   c_start[6]  = {15, 15, 14, 12, 8, 0};
__constant__ int   c_roff[6]   = {0, 1, 3, 7, 15, 31};
__constant__ float c_wsc[6]    = {1.f, 0.5f, 0.25f, 0.125f, 0.0625f, 0.03125f};

struct DecP { const float* W[6]; const float* Bx[6]; };

__global__ void __launch_bounds__(512)
decode_kernel(const float* __restrict__ x, DecP P, float* __restrict__ xhat_out)
{
    __shared__ int   sidx[KTOP];
    __shared__ float sval[KTOP];
    __shared__ float red[512];

    const int b = blockIdx.x;
    const int tid = threadIdx.x;
    if (tid < KTOP) {
        sidx[tid] = g_idx[b * KTOP + tid];
        sval[tid] = g_val[b * KTOP + tid];
    }
    __syncthreads();

    float lsum = 0.f;
    for (int s = tid; s < 63 * 128; s += 512) {
        const int r = s >> 7;
        const int col = (s & 127) << 2;
        const int sc = (r >= 31) ? 5 : (r >= 15) ? 4 : (r >= 7) ? 3
                     : (r >= 3) ? 2 : (r >= 1) ? 1 : 0;
        const int tp = r - c_roff[sc];
        const int stride = c_stride[sc];
        const int pref = c_prefix[sc];
        const float* Wb = P.W[sc] + (size_t)tp * 512 + col;

        float4 acc = make_float4(0.f, 0.f, 0.f, 0.f);
#pragma unroll 4
        for (int j = 0; j < KTOP; j++) {
            int f = sidx[j];
            if (f < pref) {
                float v = sval[j];
                float4 w = *(const float4*)(Wb + (size_t)f * stride);
                acc.x = fmaf(v, w.x, acc.x);
                acc.y = fmaf(v, w.y, acc.y);
                acc.z = fmaf(v, w.z, acc.z);
                acc.w = fmaf(v, w.w, acc.w);
            }
        }
        float4 bb = *(const float4*)(P.Bx[sc] + (size_t)tp * 512 + col);
        acc.x += bb.x; acc.y += bb.y; acc.z += bb.z; acc.w += bb.w;

        const float4 xv = *(const float4*)(x + ((size_t)b * 32 + c_start[sc] + tp) * 512 + col);
        float d0 = acc.x - xv.x, d1 = acc.y - xv.y;
        float d2 = acc.z - xv.z, d3 = acc.w - xv.w;
        lsum += c_wsc[sc] * (d0 * d0 + d1 * d1 + d2 * d2 + d3 * d3);

        if (sc == 5) {
            float* o = xhat_out + ((size_t)b * 32 + tp) * 512 + col;
            o[0] = acc.x; o[1] = acc.y; o[2] = acc.z; o[3] = acc.w;
        }
    }

    red[tid] = lsum;
    __syncthreads();
    for (int off = 256; off > 0; off >>= 1) {
        if (tid < off) red[tid] += red[tid + off];
        __syncthreads();
    }
    if (tid == 0) g_part[b] = red[0];
}

// =====================================================================
// Kernel 4: deterministic final loss reduction (double precision).
// total = sum_b P_b / (B * N_SCALES) = sum / 6144
// =====================================================================
__global__ void __launch_bounds__(256)
finalize_kernel(float* __restrict__ out)
{
    __shared__ double red[256];
    const int t = threadIdx.x;
    double s = 0.0;
    for (int i = t; i < B_SZ; i += 256) s += (double)g_part[i];
    red[t] = s;
    __syncthreads();
    for (int off = 128; off > 0; off >>= 1) {
        if (t < off) red[t] += red[t + off];
        __syncthreads();
    }
    if (t == 0) out[0] = (float)(red[0] / 6144.0);
}

// =====================================================================
extern "C" void kernel_launch(void* const* d_in, const int* in_sizes, int n_in,
                              void* d_out, int out_size)
{
    const float* x  = (const float*)d_in[0];
    const float* We = (const float*)d_in[1];
    const float* be = (const float*)d_in[2];

    DecP P;
    if (n_in >= 15 && in_sizes[4] == 512) {
        // interleaved: W_dec_0, b_dec_0, W_dec_1, b_dec_1, ...
        for (int i = 0; i < 6; i++) {
            P.W[i]  = (const float*)d_in[3 + 2 * i];
            P.Bx[i] = (const float*)d_in[4 + 2 * i];
        }
    } else {
        // grouped: W_dec_0..5 then b_dec_0..5
        for (int i = 0; i < 6; i++) {
            P.W[i]  = (const float*)d_in[3 + i];
            P.Bx[i] = (const float*)d_in[9 + i];
        }
    }

    float* out  = (float*)d_out;
    float* xhat = out + 1;                                  // (1024,32,512), 4B-aligned!
    float* z    = out + 1 + (size_t)B_SZ * 32 * 512;        // (1024,8192), 4B-aligned!

    enc_gemm<<<dim3(64, 8), 256>>>(x, We, be);
    topk_kernel<<<B_SZ, 256>>>(z);
    decode_kernel<<<B_SZ, 512>>>(x, P, xhat);
    finalize_kernel<<<1, 256>>>(out);
}

// round 12
// speedup vs baseline: 1.4130x; 1.4130x over previous
#include <cuda_runtime.h>
#include <cuda_bf16.h>
#include <mma.h>
#include <cstdint>
#include <cstddef>

using namespace nvcuda;

#define B_SZ 1024
#define DSAE 8192
#define KDIM 16384
#define KTOP 64

typedef unsigned long long ull;
typedef unsigned int uint32;

// ---------------- static scratch (no allocations allowed) ----------------
__device__ float g_pre[(size_t)B_SZ * DSAE];   // 32 MB encoder output (pre-bias)
__device__ int   g_idx[B_SZ * KTOP];
__device__ float g_val[B_SZ * KTOP];
__device__ float g_part[B_SZ];
// bf16 hi/lo decompositions (W kept in native [k][n] layout — row-major matrix_b)
__device__ __nv_bfloat16 g_Xhi[(size_t)B_SZ * KDIM];
__device__ __nv_bfloat16 g_Xlo[(size_t)B_SZ * KDIM];
__device__ __nv_bfloat16 g_Whi[(size_t)KDIM * DSAE];
__device__ __nv_bfloat16 g_Wlo[(size_t)KDIM * DSAE];

// ---------------- helpers ----------------
__device__ __forceinline__ uint32 smem_u32(const void* p) {
    uint32 a;
    asm("{ .reg .u64 t; cvta.to.shared.u64 t, %1; cvt.u32.u64 %0, t; }"
        : "=r"(a) : "l"(p));
    return a;
}
__device__ __forceinline__ void cp16(uint32 dst, const void* src) {
    asm volatile("cp.async.ca.shared.global [%0], [%1], 16;"
                 :: "r"(dst), "l"(src));
}
#define CP_COMMIT() asm volatile("cp.async.commit_group;" ::: "memory")
#define CP_WAIT1()  asm volatile("cp.async.wait_group 1;" ::: "memory")

// =====================================================================
// Kernel 0: fp32 -> bf16 hi/lo split (2 elems/thread)
// =====================================================================
__global__ void __launch_bounds__(256)
conv_split(const float* __restrict__ src, __nv_bfloat16* __restrict__ hi,
           __nv_bfloat16* __restrict__ lo)
{
    size_t i = ((size_t)blockIdx.x * 256 + threadIdx.x) * 2;
    float2 v = *(const float2*)(src + i);
    __nv_bfloat16 h0 = __float2bfloat16(v.x);
    __nv_bfloat16 h1 = __float2bfloat16(v.y);
    __nv_bfloat16 l0 = __float2bfloat16(v.x - __bfloat162float(h0));
    __nv_bfloat16 l1 = __float2bfloat16(v.y - __bfloat162float(h1));
    *(__nv_bfloat162*)(hi + i) = __nv_bfloat162(h0, h1);
    *(__nv_bfloat162*)(lo + i) = __nv_bfloat162(l0, l1);
}

// =====================================================================
// Kernel 1: encoder GEMM via WMMA bf16 split (3 products: hh, hl, lh).
//   g_pre[1024][8192] = X[1024][16384] * W[16384][8192]  (bias in topk)
// CTA 128x128, 256 thr (8 warps, 4m x 2n of 32x64 tiles), KC=64,
// 3-stage cp.async pipeline on pre-split bf16 arrays.
// =====================================================================
#define KC        64
#define A_PITCH_B 144                  // 72 bf16
#define B_PITCH_B 272                  // 136 bf16
#define ST_AHI    0
#define ST_ALO    18432
#define ST_BHI    36864
#define ST_BLO    54272
#define STAGE_B   71680
#define NSTAGE    3
#define NCHUNK    (KDIM / KC)          // 256

typedef wmma::fragment<wmma::matrix_a, 16, 16, 16, __nv_bfloat16, wmma::row_major> FA;
typedef wmma::fragment<wmma::matrix_b, 16, 16, 16, __nv_bfloat16, wmma::row_major> FB;
typedef wmma::fragment<wmma::accumulator, 16, 16, 16, float> FC;

__global__ void __launch_bounds__(256, 1)
enc_wmma()
{
    extern __shared__ __align__(16) char smem[];
    const int tid = threadIdx.x;
    const int wid = tid >> 5;
    const int wm  = wid & 3;        // 0..3 -> 32-row slice
    const int wn  = wid >> 2;       // 0..1 -> 64-col slice
    const int bn  = blockIdx.x;     // 0..63
    const int bm  = blockIdx.y;     // 0..7
    const uint32 sb = smem_u32(smem);

    auto issue = [&](int c) {
        const uint32 base = sb + (uint32)(c % NSTAGE) * STAGE_B;
#pragma unroll
        for (int comp = 0; comp < 2; comp++) {
            const __nv_bfloat16* xs = (comp ? g_Xlo : g_Xhi)
                + (size_t)(bm * 128) * KDIM + c * KC;
            const uint32 abase = base + (comp ? ST_ALO : ST_AHI);
#pragma unroll
            for (int it = 0; it < 4; it++) {
                const int idx = tid + it * 256;
                const int row = idx >> 3, seg = idx & 7;
                cp16(abase + row * A_PITCH_B + seg * 16,
                     xs + (size_t)row * KDIM + seg * 8);
            }
        }
#pragma unroll
        for (int comp = 0; comp < 2; comp++) {
            const __nv_bfloat16* ws = (comp ? g_Wlo : g_Whi)
                + (size_t)(c * KC) * DSAE + bn * 128;
            const uint32 bbase = base + (comp ? ST_BLO : ST_BHI);
#pragma unroll
            for (int it = 0; it < 4; it++) {
                const int idx = tid + it * 256;
                const int k = idx >> 4, seg = idx & 15;
                cp16(bbase + k * B_PITCH_B + seg * 16,
                     ws + (size_t)k * DSAE + seg * 8);
            }
        }
        CP_COMMIT();
    };

    FC acc[2][4];
#pragma unroll
    for (int i = 0; i < 2; i++)
#pragma unroll
        for (int j = 0; j < 4; j++) wmma::fill_fragment(acc[i][j], 0.0f);

    issue(0);
    issue(1);

    for (int c = 0; c < NCHUNK; c++) {
        CP_WAIT1();
        __syncthreads();
        if (c + 2 < NCHUNK) issue(c + 2);

        const char* st = smem + (size_t)(c % NSTAGE) * STAGE_B;
        const __nv_bfloat16* Ah = (const __nv_bfloat16*)(st + ST_AHI);
        const __nv_bfloat16* Al = (const __nv_bfloat16*)(st + ST_ALO);
        const __nv_bfloat16* Bh = (const __nv_bfloat16*)(st + ST_BHI);
        const __nv_bfloat16* Bl = (const __nv_bfloat16*)(st + ST_BLO);

#pragma unroll
        for (int ks = 0; ks < KC / 16; ks++) {
            FA ah[2], al[2];
            FB bh[4], bl[4];
#pragma unroll
            for (int mi = 0; mi < 2; mi++) {
                const int r = (wm * 32 + mi * 16) * 72 + ks * 16;
                wmma::load_matrix_sync(ah[mi], Ah + r, 72);
                wmma::load_matrix_sync(al[mi], Al + r, 72);
            }
#pragma unroll
            for (int ni = 0; ni < 4; ni++) {
                const int r = (ks * 16) * 136 + wn * 64 + ni * 16;
                wmma::load_matrix_sync(bh[ni], Bh + r, 136);
                wmma::load_matrix_sync(bl[ni], Bl + r, 136);
            }
#pragma unroll
            for (int mi = 0; mi < 2; mi++)
#pragma unroll
                for (int ni = 0; ni < 4; ni++) {
                    wmma::mma_sync(acc[mi][ni], ah[mi], bh[ni], acc[mi][ni]);
                    wmma::mma_sync(acc[mi][ni], ah[mi], bl[ni], acc[mi][ni]);
                    wmma::mma_sync(acc[mi][ni], al[mi], bh[ni], acc[mi][ni]);
                }
        }
    }

#pragma unroll
    for (int mi = 0; mi < 2; mi++)
#pragma unroll
        for (int ni = 0; ni < 4; ni++) {
            float* dst = g_pre
                + (size_t)(bm * 128 + wm * 32 + mi * 16) * DSAE
                + bn * 128 + wn * 64 + ni * 16;
            wmma::store_matrix_sync(dst, acc[mi][ni], DSAE, wmma::mem_row_major);
        }
}

// =====================================================================
// Kernel 2: top-64 per row. Radix select on approximate keys; entries in
// the ambiguity band [thr-WIN, thr+WIN] get exact fp32 recompute when the
// band is contested. Guarantees exact top-64 SET for |approx err| < WIN/2.
// =====================================================================
#define WIN 4e-3f

__global__ void __launch_bounds__(256)
topk_kernel(const float* __restrict__ X, const float* __restrict__ Wenc,
            const float* __restrict__ bias, float* __restrict__ z_out)
{
    extern __shared__ __align__(16) char dsm[];
    uint32* keys = (uint32*)dsm;                 // 32 KB
    float*  vals = (float*)(dsm + 32768);        // 32 KB

    __shared__ uint32 hist[256];
    __shared__ uint32 tieb_[256];
    __shared__ float  red[256];
    __shared__ int    selidx[KTOP];
    __shared__ float  selval[KTOP];
    __shared__ int    ambidx[KTOP];
    __shared__ float  ambval[KTOP];
    __shared__ float  ambex[KTOP];
    __shared__ uint32 s_pref, s_mask;
    __shared__ int    s_kneed, s_ncert, s_namb;

    const int b = blockIdx.x;
    const int tid = threadIdx.x;
    const float* pre = g_pre + (size_t)b * DSAE;
    float* zr = z_out + (size_t)b * DSAE;

    for (int i = tid; i < 8192; i += 256) {
        float v = pre[i] + bias[i];
        vals[i] = v;
        uint32 u = __float_as_uint(v);
        keys[i] = (u & 0x80000000u) ? ~u : (u | 0x80000000u);
        zr[i] = 0.f;
    }
    if (tid == 0) { s_pref = 0u; s_mask = 0u; s_kneed = KTOP; s_ncert = 0; s_namb = 0; }
    __syncthreads();

    // 4-level radix select for the 64th key
    for (int lvl = 0; lvl < 4; lvl++) {
        const int shift = 24 - lvl * 8;
        hist[tid] = 0u;
        __syncthreads();
        const uint32 msk = s_mask, prf = s_pref;
        for (int i = tid; i < 8192; i += 256) {
            uint32 k = keys[i];
            if ((k & msk) == prf) atomicAdd(&hist[(k >> shift) & 255u], 1u);
        }
        __syncthreads();
        if (tid == 0) {
            int need = s_kneed, cum = 0, d = 255;
            for (; d >= 0; d--) {
                int c = (int)hist[d];
                if (cum + c >= need) { s_kneed = need - cum; break; }
                cum += c;
            }
            s_pref = prf | ((uint32)d << shift);
            s_mask = msk | (0xFFu << shift);
        }
        __syncthreads();
    }

    const uint32 Kthr = s_pref;
    uint32 ub = (Kthr & 0x80000000u) ? (Kthr ^ 0x80000000u) : ~Kthr;
    const float thr_v = __uint_as_float(ub);

    // classification: certain (> thr+WIN), ambiguous ([thr-WIN, thr+WIN])
    for (int i = tid; i < 8192; i += 256) {
        float v = vals[i];
        if (v > thr_v + WIN) {
            int p = atomicAdd(&s_ncert, 1);
            if (p < KTOP) { selidx[p] = i; selval[p] = v; }
        } else if (v >= thr_v - WIN) {
            int p = atomicAdd(&s_namb, 1);
            if (p < KTOP) { ambidx[p] = i; ambval[p] = v; }
        }
    }
    __syncthreads();

    const int ncert = min(s_ncert, KTOP);
    const int namb  = min(s_namb, KTOP);
    const int slots = KTOP - ncert;

    if (namb > slots) {
        // contested band: exact fp32 recompute (deterministic tree reduction)
        const float* xr = X + (size_t)b * KDIM;
        for (int j = 0; j < namb; j++) {
            const int f = ambidx[j];
            float part = 0.f;
            for (int k = tid; k < KDIM; k += 256)
                part = fmaf(xr[k], Wenc[(size_t)k * DSAE + f], part);
            red[tid] = part;
            __syncthreads();
            for (int off = 128; off > 0; off >>= 1) {
                if (tid < off) red[tid] += red[tid + off];
                __syncthreads();
            }
            if (tid == 0) ambex[j] = red[0] + bias[f];
            __syncthreads();
        }
    } else {
        if (tid < namb) ambex[tid] = ambval[tid];
        __syncthreads();
    }

    // pick top `slots` of the band by (exact desc, index asc)
    if (tid == 0) {
        unsigned char used[KTOP];
        for (int j = 0; j < namb; j++) used[j] = 0;
        for (int t = 0; t < slots; t++) {
            int best = -1;
            for (int j = 0; j < namb; j++) {
                if (used[j]) continue;
                if (best < 0 || ambex[j] > ambex[best] ||
                    (ambex[j] == ambex[best] && ambidx[j] < ambidx[best]))
                    best = j;
            }
            used[best] = 1;
            selidx[ncert + t] = ambidx[best];
            selval[ncert + t] = ambex[best];
        }
    }
    __syncthreads();

    if (tid < KTOP) {
        int   fi = selidx[tid];
        float fv = fmaxf(selval[tid], 0.f);
        g_idx[b * KTOP + tid] = fi;
        g_val[b * KTOP + tid] = fv;
        zr[fi] = fv;
    }
}

// =====================================================================
// Kernel 3: sparse multi-scale decode + loss partials + last_xhat.
// =====================================================================
__constant__ int   c_prefix[6] = {1366, 2732, 4097, 5462, 6827, 8192};
__constant__ int   c_stride[6] = {512, 1024, 2048, 4096, 8192, 16384};
__constant__ int   c_start[6]  = {15, 15, 14, 12, 8, 0};
__constant__ int   c_roff[6]   = {0, 1, 3, 7, 15, 31};
__constant__ float c_wsc[6]    = {1.f, 0.5f, 0.25f, 0.125f, 0.0625f, 0.03125f};

struct DecP { const float* W[6]; const float* Bx[6]; };

__global__ void __launch_bounds__(512)
decode_kernel(const float* __restrict__ x, DecP P, float* __restrict__ xhat_out)
{
    __shared__ int   sidx[KTOP];
    __shared__ float sval[KTOP];
    __shared__ float red[512];

    const int b = blockIdx.x;
    const int tid = threadIdx.x;
    if (tid < KTOP) {
        sidx[tid] = g_idx[b * KTOP + tid];
        sval[tid] = g_val[b * KTOP + tid];
    }
    __syncthreads();

    float lsum = 0.f;
    for (int s = tid; s < 63 * 128; s += 512) {
        const int r = s >> 7;
        const int col = (s & 127) << 2;
        const int sc = (r >= 31) ? 5 : (r >= 15) ? 4 : (r >= 7) ? 3
                     : (r >= 3) ? 2 : (r >= 1) ? 1 : 0;
        const int tp = r - c_roff[sc];
        const int stride = c_stride[sc];
        const int pref = c_prefix[sc];
        const float* Wb = P.W[sc] + (size_t)tp * 512 + col;

        float4 acc = make_float4(0.f, 0.f, 0.f, 0.f);
#pragma unroll 4
        for (int j = 0; j < KTOP; j++) {
            int f = sidx[j];
            if (f < pref) {
                float v = sval[j];
                float4 w = *(const float4*)(Wb + (size_t)f * stride);
                acc.x = fmaf(v, w.x, acc.x);
                acc.y = fmaf(v, w.y, acc.y);
                acc.z = fmaf(v, w.z, acc.z);
                acc.w = fmaf(v, w.w, acc.w);
            }
        }
        float4 bb = *(const float4*)(P.Bx[sc] + (size_t)tp * 512 + col);
        acc.x += bb.x; acc.y += bb.y; acc.z += bb.z; acc.w += bb.w;

        const float4 xv = *(const float4*)(x + ((size_t)b * 32 + c_start[sc] + tp) * 512 + col);
        float d0 = acc.x - xv.x, d1 = acc.y - xv.y;
        float d2 = acc.z - xv.z, d3 = acc.w - xv.w;
        lsum += c_wsc[sc] * (d0 * d0 + d1 * d1 + d2 * d2 + d3 * d3);

        if (sc == 5) {
            float* o = xhat_out + ((size_t)b * 32 + tp) * 512 + col;
            o[0] = acc.x; o[1] = acc.y; o[2] = acc.z; o[3] = acc.w;
        }
    }

    red[tid] = lsum;
    __syncthreads();
    for (int off = 256; off > 0; off >>= 1) {
        if (tid < off) red[tid] += red[tid + off];
        __syncthreads();
    }
    if (tid == 0) g_part[b] = red[0];
}

// =====================================================================
// Kernel 4: deterministic final loss reduction.
// =====================================================================
__global__ void __launch_bounds__(256)
finalize_kernel(float* __restrict__ out)
{
    __shared__ double red[256];
    const int t = threadIdx.x;
    double s = 0.0;
    for (int i = t; i < B_SZ; i += 256) s += (double)g_part[i];
    red[t] = s;
    __syncthreads();
    for (int off = 128; off > 0; off >>= 1) {
        if (t < off) red[t] += red[t + off];
        __syncthreads();
    }
    if (t == 0) out[0] = (float)(red[0] / 6144.0);
}

// =====================================================================
extern "C" void kernel_launch(void* const* d_in, const int* in_sizes, int n_in,
                              void* d_out, int out_size)
{
    const float* x  = (const float*)d_in[0];
    const float* We = (const float*)d_in[1];
    const float* be = (const float*)d_in[2];

    DecP P;
    if (n_in >= 15 && in_sizes[4] == 512) {
        for (int i = 0; i < 6; i++) {
            P.W[i]  = (const float*)d_in[3 + 2 * i];
            P.Bx[i] = (const float*)d_in[4 + 2 * i];
        }
    } else {
        for (int i = 0; i < 6; i++) {
            P.W[i]  = (const float*)d_in[3 + i];
            P.Bx[i] = (const float*)d_in[9 + i];
        }
    }

    float* out  = (float*)d_out;
    float* xhat = out + 1;                                  // (1024,32,512), 4B-aligned
    float* z    = out + 1 + (size_t)B_SZ * 32 * 512;        // (1024,8192), 4B-aligned

    cudaFuncSetAttribute(enc_wmma,
        cudaFuncAttributeMaxDynamicSharedMemorySize, NSTAGE * STAGE_B);
    cudaFuncSetAttribute(topk_kernel,
        cudaFuncAttributeMaxDynamicSharedMemorySize, 65536);

    __nv_bfloat16 *xhi, *xlo, *whi, *wlo;
    cudaGetSymbolAddress((void**)&xhi, g_Xhi);
    cudaGetSymbolAddress((void**)&xlo, g_Xlo);
    cudaGetSymbolAddress((void**)&whi, g_Whi);
    cudaGetSymbolAddress((void**)&wlo, g_Wlo);

    conv_split<<<(B_SZ * KDIM) / 512, 256>>>(x, xhi, xlo);
    conv_split<<<((size_t)KDIM * DSAE) / 512, 256>>>(We, whi, wlo);
    enc_wmma<<<dim3(64, 8), 256, NSTAGE * STAGE_B>>>();
    topk_kernel<<<B_SZ, 256, 65536>>>(x, We, be, z);
    decode_kernel<<<B_SZ, 512>>>(x, P, xhat);
    finalize_kernel<<<1, 256>>>(out);
}

// round 13
// speedup vs baseline: 1.6932x; 1.1983x over previous
#include <cuda_runtime.h>
#include <cuda_bf16.h>
#include <mma.h>
#include <cstdint>
#include <cstddef>

using namespace nvcuda;

#define B_SZ 1024
#define DSAE 8192
#define KDIM 16384
#define KTOP 64

typedef unsigned long long ull;
typedef unsigned int uint32;

// ---------------- static scratch (no allocations allowed) ----------------
__device__ float g_pre[(size_t)B_SZ * DSAE];   // 32 MB encoder output (pre-bias)
__device__ int   g_idx[B_SZ * KTOP];
__device__ float g_val[B_SZ * KTOP];
__device__ float g_part[B_SZ];
// bf16 hi/lo decompositions (W kept in native [k][n] layout — row-major matrix_b)
__device__ __nv_bfloat16 g_Xhi[(size_t)B_SZ * KDIM];
__device__ __nv_bfloat16 g_Xlo[(size_t)B_SZ * KDIM];
__device__ __nv_bfloat16 g_Whi[(size_t)KDIM * DSAE];
__device__ __nv_bfloat16 g_Wlo[(size_t)KDIM * DSAE];

// ---------------- helpers ----------------
__device__ __forceinline__ uint32 smem_u32(const void* p) {
    uint32 a;
    asm("{ .reg .u64 t; cvta.to.shared.u64 t, %1; cvt.u32.u64 %0, t; }"
        : "=r"(a) : "l"(p));
    return a;
}
__device__ __forceinline__ void cp16(uint32 dst, const void* src) {
    asm volatile("cp.async.ca.shared.global [%0], [%1], 16;"
                 :: "r"(dst), "l"(src));
}
#define CP_COMMIT() asm volatile("cp.async.commit_group;" ::: "memory")
#define CP_WAIT1()  asm volatile("cp.async.wait_group 1;" ::: "memory")

// =====================================================================
// Kernel 0: fp32 -> bf16 hi/lo split (2 elems/thread)
// =====================================================================
__global__ void __launch_bounds__(256)
conv_split(const float* __restrict__ src, __nv_bfloat16* __restrict__ hi,
           __nv_bfloat16* __restrict__ lo)
{
    size_t i = ((size_t)blockIdx.x * 256 + threadIdx.x) * 2;
    float2 v = *(const float2*)(src + i);
    __nv_bfloat16 h0 = __float2bfloat16(v.x);
    __nv_bfloat16 h1 = __float2bfloat16(v.y);
    __nv_bfloat16 l0 = __float2bfloat16(v.x - __bfloat162float(h0));
    __nv_bfloat16 l1 = __float2bfloat16(v.y - __bfloat162float(h1));
    *(__nv_bfloat162*)(hi + i) = __nv_bfloat162(h0, h1);
    *(__nv_bfloat162*)(lo + i) = __nv_bfloat162(l0, l1);
}

// =====================================================================
// Kernel 1: encoder GEMM via WMMA bf16 split (3 products: hh, hl, lh).
//   g_pre[1024][8192] = X[1024][16384] * W[16384][8192]  (bias in topk)
// CTA 256x128, 256 thr (8 warps, 4m x 2n grid of 64x64 warp tiles), KC=32,
// 3-stage cp.async pipeline on pre-split bf16 arrays.
// =====================================================================
#define KC        32
#define A_PITCH   40                   // bf16 units (80 B rows, 16B-aligned)
#define B_PITCH   136                  // bf16 units (272 B rows)
#define ST_AHI    0
#define ST_ALO    20480                // 256*40*2B
#define ST_BHI    40960
#define ST_BLO    49664                // +32*136*2B
#define STAGE_B   58368
#define NSTAGE    3
#define NCHUNK    (KDIM / KC)          // 512

typedef wmma::fragment<wmma::matrix_a, 16, 16, 16, __nv_bfloat16, wmma::row_major> FA;
typedef wmma::fragment<wmma::matrix_b, 16, 16, 16, __nv_bfloat16, wmma::row_major> FB;
typedef wmma::fragment<wmma::accumulator, 16, 16, 16, float> FC;

__global__ void __launch_bounds__(256, 1)
enc_wmma()
{
    extern __shared__ __align__(16) char smem[];
    const int tid = threadIdx.x;
    const int wid = tid >> 5;
    const int wm  = wid & 3;        // 0..3 -> 64-row slice of 256
    const int wn  = wid >> 2;       // 0..1 -> 64-col slice of 128
    const int bn  = blockIdx.x;     // 0..63
    const int bm  = blockIdx.y;     // 0..3
    const uint32 sb = smem_u32(smem);

    auto issue = [&](int c) {
        const uint32 base = sb + (uint32)(c % NSTAGE) * STAGE_B;
#pragma unroll
        for (int comp = 0; comp < 2; comp++) {
            const __nv_bfloat16* xs = (comp ? g_Xlo : g_Xhi)
                + (size_t)(bm * 256) * KDIM + c * KC;
            const uint32 abase = base + (comp ? ST_ALO : ST_AHI);
#pragma unroll
            for (int it = 0; it < 4; it++) {
                const int idx = tid + it * 256;
                const int row = idx >> 2, seg = idx & 3;   // 256 rows x 4 segs
                cp16(abase + row * (A_PITCH * 2) + seg * 16,
                     xs + (size_t)row * KDIM + seg * 8);
            }
        }
#pragma unroll
        for (int comp = 0; comp < 2; comp++) {
            const __nv_bfloat16* ws = (comp ? g_Wlo : g_Whi)
                + (size_t)(c * KC) * DSAE + bn * 128;
            const uint32 bbase = base + (comp ? ST_BLO : ST_BHI);
#pragma unroll
            for (int it = 0; it < 2; it++) {
                const int idx = tid + it * 256;
                const int k = idx >> 4, seg = idx & 15;    // 32 k x 16 segs
                cp16(bbase + k * (B_PITCH * 2) + seg * 16,
                     ws + (size_t)k * DSAE + seg * 8);
            }
        }
        CP_COMMIT();
    };

    FC acc[4][4];
#pragma unroll
    for (int i = 0; i < 4; i++)
#pragma unroll
        for (int j = 0; j < 4; j++) wmma::fill_fragment(acc[i][j], 0.0f);

    issue(0);
    issue(1);

    for (int c = 0; c < NCHUNK; c++) {
        CP_WAIT1();
        __syncthreads();
        if (c + 2 < NCHUNK) issue(c + 2);

        const char* st = smem + (size_t)(c % NSTAGE) * STAGE_B;
        const __nv_bfloat16* Ah = (const __nv_bfloat16*)(st + ST_AHI);
        const __nv_bfloat16* Al = (const __nv_bfloat16*)(st + ST_ALO);
        const __nv_bfloat16* Bh = (const __nv_bfloat16*)(st + ST_BHI);
        const __nv_bfloat16* Bl = (const __nv_bfloat16*)(st + ST_BLO);

#pragma unroll
        for (int ks = 0; ks < KC / 16; ks++) {
            FA ah[4], al[4];
            FB bh[4], bl[4];
#pragma unroll
            for (int mi = 0; mi < 4; mi++) {
                const int r = (wm * 64 + mi * 16) * A_PITCH + ks * 16;
                wmma::load_matrix_sync(ah[mi], Ah + r, A_PITCH);
                wmma::load_matrix_sync(al[mi], Al + r, A_PITCH);
            }
#pragma unroll
            for (int ni = 0; ni < 4; ni++) {
                const int r = (ks * 16) * B_PITCH + wn * 64 + ni * 16;
                wmma::load_matrix_sync(bh[ni], Bh + r, B_PITCH);
                wmma::load_matrix_sync(bl[ni], Bl + r, B_PITCH);
            }
#pragma unroll
            for (int mi = 0; mi < 4; mi++)
#pragma unroll
                for (int ni = 0; ni < 4; ni++) {
                    wmma::mma_sync(acc[mi][ni], ah[mi], bh[ni], acc[mi][ni]);
                    wmma::mma_sync(acc[mi][ni], ah[mi], bl[ni], acc[mi][ni]);
                    wmma::mma_sync(acc[mi][ni], al[mi], bh[ni], acc[mi][ni]);
                }
        }
    }

#pragma unroll
    for (int mi = 0; mi < 4; mi++)
#pragma unroll
        for (int ni = 0; ni < 4; ni++) {
            float* dst = g_pre
                + (size_t)(bm * 256 + wm * 64 + mi * 16) * DSAE
                + bn * 128 + wn * 64 + ni * 16;
            wmma::store_matrix_sync(dst, acc[mi][ni], DSAE, wmma::mem_row_major);
        }
}

// =====================================================================
// Kernel 2: top-64 per row. Radix select on approximate keys; entries in
// the ambiguity band [thr-WIN, thr+WIN] get exact fp32 recompute when the
// band is contested. Guarantees exact top-64 SET for |approx err| < WIN/2.
// =====================================================================
#define WIN 4e-3f

__global__ void __launch_bounds__(256)
topk_kernel(const float* __restrict__ X, const float* __restrict__ Wenc,
            const float* __restrict__ bias, float* __restrict__ z_out)
{
    extern __shared__ __align__(16) char dsm[];
    uint32* keys = (uint32*)dsm;                 // 32 KB
    float*  vals = (float*)(dsm + 32768);        // 32 KB

    __shared__ uint32 hist[256];
    __shared__ float  red[256];
    __shared__ int    selidx[KTOP];
    __shared__ float  selval[KTOP];
    __shared__ int    ambidx[KTOP];
    __shared__ float  ambval[KTOP];
    __shared__ float  ambex[KTOP];
    __shared__ uint32 s_pref, s_mask;
    __shared__ int    s_kneed, s_ncert, s_namb;

    const int b = blockIdx.x;
    const int tid = threadIdx.x;
    const float* pre = g_pre + (size_t)b * DSAE;
    float* zr = z_out + (size_t)b * DSAE;

    for (int i = tid; i < 8192; i += 256) {
        float v = pre[i] + bias[i];
        vals[i] = v;
        uint32 u = __float_as_uint(v);
        keys[i] = (u & 0x80000000u) ? ~u : (u | 0x80000000u);
        zr[i] = 0.f;
    }
    if (tid == 0) { s_pref = 0u; s_mask = 0u; s_kneed = KTOP; s_ncert = 0; s_namb = 0; }
    __syncthreads();

    // 4-level radix select for the 64th key
    for (int lvl = 0; lvl < 4; lvl++) {
        const int shift = 24 - lvl * 8;
        hist[tid] = 0u;
        __syncthreads();
        const uint32 msk = s_mask, prf = s_pref;
        for (int i = tid; i < 8192; i += 256) {
            uint32 k = keys[i];
            if ((k & msk) == prf) atomicAdd(&hist[(k >> shift) & 255u], 1u);
        }
        __syncthreads();
        if (tid == 0) {
            int need = s_kneed, cum = 0, d = 255;
            for (; d >= 0; d--) {
                int c = (int)hist[d];
                if (cum + c >= need) { s_kneed = need - cum; break; }
                cum += c;
            }
            s_pref = prf | ((uint32)d << shift);
            s_mask = msk | (0xFFu << shift);
        }
        __syncthreads();
    }

    const uint32 Kthr = s_pref;
    uint32 ub = (Kthr & 0x80000000u) ? (Kthr ^ 0x80000000u) : ~Kthr;
    const float thr_v = __uint_as_float(ub);

    // classification: certain (> thr+WIN), ambiguous ([thr-WIN, thr+WIN])
    for (int i = tid; i < 8192; i += 256) {
        float v = vals[i];
        if (v > thr_v + WIN) {
            int p = atomicAdd(&s_ncert, 1);
            if (p < KTOP) { selidx[p] = i; selval[p] = v; }
        } else if (v >= thr_v - WIN) {
            int p = atomicAdd(&s_namb, 1);
            if (p < KTOP) { ambidx[p] = i; ambval[p] = v; }
        }
    }
    __syncthreads();

    const int ncert = min(s_ncert, KTOP);
    const int namb  = min(s_namb, KTOP);
    const int slots = KTOP - ncert;

    if (namb > slots) {
        // contested band: exact fp32 recompute (deterministic tree reduction)
        const float* xr = X + (size_t)b * KDIM;
        for (int j = 0; j < namb; j++) {
            const int f = ambidx[j];
            float part = 0.f;
            for (int k = tid; k < KDIM; k += 256)
                part = fmaf(xr[k], Wenc[(size_t)k * DSAE + f], part);
            red[tid] = part;
            __syncthreads();
            for (int off = 128; off > 0; off >>= 1) {
                if (tid < off) red[tid] += red[tid + off];
                __syncthreads();
            }
            if (tid == 0) ambex[j] = red[0] + bias[f];
            __syncthreads();
        }
    } else {
        if (tid < namb) ambex[tid] = ambval[tid];
        __syncthreads();
    }

    // pick top `slots` of the band by (exact desc, index asc)
    if (tid == 0) {
        unsigned char used[KTOP];
        for (int j = 0; j < namb; j++) used[j] = 0;
        for (int t = 0; t < slots; t++) {
            int best = -1;
            for (int j = 0; j < namb; j++) {
                if (used[j]) continue;
                if (best < 0 || ambex[j] > ambex[best] ||
                    (ambex[j] == ambex[best] && ambidx[j] < ambidx[best]))
                    best = j;
            }
            used[best] = 1;
            selidx[ncert + t] = ambidx[best];
            selval[ncert + t] = ambex[best];
        }
    }
    __syncthreads();

    if (tid < KTOP) {
        int   fi = selidx[tid];
        float fv = fmaxf(selval[tid], 0.f);
        g_idx[b * KTOP + tid] = fi;
        g_val[b * KTOP + tid] = fv;
        zr[fi] = fv;
    }
}

// =====================================================================
// Kernel 3: sparse multi-scale decode + loss partials + last_xhat.
// =====================================================================
__constant__ int   c_prefix[6] = {1366, 2732, 4097, 5462, 6827, 8192};
__constant__ int   c_stride[6] = {512, 1024, 2048, 4096, 8192, 16384};
__constant__ int   c_start[6]  = {15, 15, 14, 12, 8, 0};
__constant__ int   c_roff[6]   = {0, 1, 3, 7, 15, 31};
__constant__ float c_wsc[6]    = {1.f, 0.5f, 0.25f, 0.125f, 0.0625f, 0.03125f};

struct DecP { const float* W[6]; const float* Bx[6]; };

__global__ void __launch_bounds__(512)
decode_kernel(const float* __restrict__ x, DecP P, float* __restrict__ xhat_out)
{
    __shared__ int   sidx[KTOP];
    __shared__ float sval[KTOP];
    __shared__ float red[512];

    const int b = blockIdx.x;
    const int tid = threadIdx.x;
    if (tid < KTOP) {
        sidx[tid] = g_idx[b * KTOP + tid];
        sval[tid] = g_val[b * KTOP + tid];
    }
    __syncthreads();

    float lsum = 0.f;
    for (int s = tid; s < 63 * 128; s += 512) {
        const int r = s >> 7;
        const int col = (s & 127) << 2;
        const int sc = (r >= 31) ? 5 : (r >= 15) ? 4 : (r >= 7) ? 3
                     : (r >= 3) ? 2 : (r >= 1) ? 1 : 0;
        const int tp = r - c_roff[sc];
        const int stride = c_stride[sc];
        const int pref = c_prefix[sc];
        const float* Wb = P.W[sc] + (size_t)tp * 512 + col;

        float4 acc = make_float4(0.f, 0.f, 0.f, 0.f);
#pragma unroll 4
        for (int j = 0; j < KTOP; j++) {
            int f = sidx[j];
            if (f < pref) {
                float v = sval[j];
                float4 w = *(const float4*)(Wb + (size_t)f * stride);
                acc.x = fmaf(v, w.x, acc.x);
                acc.y = fmaf(v, w.y, acc.y);
                acc.z = fmaf(v, w.z, acc.z);
                acc.w = fmaf(v, w.w, acc.w);
            }
        }
        float4 bb = *(const float4*)(P.Bx[sc] + (size_t)tp * 512 + col);
        acc.x += bb.x; acc.y += bb.y; acc.z += bb.z; acc.w += bb.w;

        const float4 xv = *(const float4*)(x + ((size_t)b * 32 + c_start[sc] + tp) * 512 + col);
        float d0 = acc.x - xv.x, d1 = acc.y - xv.y;
        float d2 = acc.z - xv.z, d3 = acc.w - xv.w;
        lsum += c_wsc[sc] * (d0 * d0 + d1 * d1 + d2 * d2 + d3 * d3);

        if (sc == 5) {
            float* o = xhat_out + ((size_t)b * 32 + tp) * 512 + col;
            o[0] = acc.x; o[1] = acc.y; o[2] = acc.z; o[3] = acc.w;
        }
    }

    red[tid] = lsum;
    __syncthreads();
    for (int off = 256; off > 0; off >>= 1) {
        if (tid < off) red[tid] += red[tid + off];
        __syncthreads();
    }
    if (tid == 0) g_part[b] = red[0];
}

// =====================================================================
// Kernel 4: deterministic final loss reduction.
// =====================================================================
__global__ void __launch_bounds__(256)
finalize_kernel(float* __restrict__ out)
{
    __shared__ double red[256];
    const int t = threadIdx.x;
    double s = 0.0;
    for (int i = t; i < B_SZ; i += 256) s += (double)g_part[i];
    red[t] = s;
    __syncthreads();
    for (int off = 128; off > 0; off >>= 1) {
        if (t < off) red[t] += red[t + off];
        __syncthreads();
    }
    if (t == 0) out[0] = (float)(red[0] / 6144.0);
}

// =====================================================================
extern "C" void kernel_launch(void* const* d_in, const int* in_sizes, int n_in,
                              void* d_out, int out_size)
{
    const float* x  = (const float*)d_in[0];
    const float* We = (const float*)d_in[1];
    const float* be = (const float*)d_in[2];

    DecP P;
    if (n_in >= 15 && in_sizes[4] == 512) {
        for (int i = 0; i < 6; i++) {
            P.W[i]  = (const float*)d_in[3 + 2 * i];
            P.Bx[i] = (const float*)d_in[4 + 2 * i];
        }
    } else {
        for (int i = 0; i < 6; i++) {
            P.W[i]  = (const float*)d_in[3 + i];
            P.Bx[i] = (const float*)d_in[9 + i];
        }
    }

    float* out  = (float*)d_out;
    float* xhat = out + 1;                                  // (1024,32,512), 4B-aligned
    float* z    = out + 1 + (size_t)B_SZ * 32 * 512;        // (1024,8192), 4B-aligned

    cudaFuncSetAttribute(enc_wmma,
        cudaFuncAttributeMaxDynamicSharedMemorySize, NSTAGE * STAGE_B);
    cudaFuncSetAttribute(topk_kernel,
        cudaFuncAttributeMaxDynamicSharedMemorySize, 65536);

    __nv_bfloat16 *xhi, *xlo, *whi, *wlo;
    cudaGetSymbolAddress((void**)&xhi, g_Xhi);
    cudaGetSymbolAddress((void**)&xlo, g_Xlo);
    cudaGetSymbolAddress((void**)&whi, g_Whi);
    cudaGetSymbolAddress((void**)&wlo, g_Wlo);

    conv_split<<<(B_SZ * KDIM) / 512, 256>>>(x, xhi, xlo);
    conv_split<<<((size_t)KDIM * DSAE) / 512, 256>>>(We, whi, wlo);
    enc_wmma<<<dim3(64, 4), 256, NSTAGE * STAGE_B>>>();
    topk_kernel<<<B_SZ, 256, 65536>>>(x, We, be, z);
    decode_kernel<<<B_SZ, 512>>>(x, P, xhat);
    finalize_kernel<<<1, 256>>>(out);
}